// round 1
// baseline (speedup 1.0000x reference)
#include <cuda_runtime.h>
#include <math.h>

#define EPS 1e-8f
#define L_FRAMES 384
#define NPTS 543
#define NLM 62
#define OUTF 744   // 5*124 + 2*62

// LANDMARKS (face 20 incl. duplicate 17, LH 501..521, RH 522..542), compile-time constant
__constant__ int c_lm[NLM] = {
    33,133,362,263,61,291,199,419,17,84,17,314,405,320,307,375,321,308,324,318,
    501,502,503,504,505,506,507,508,509,510,511,512,513,514,515,516,517,518,519,520,521,
    522,523,524,525,526,527,528,529,530,531,532,533,534,535,536,537,538,539,540,541,542
};

// per-batch stats scratch: mean_x, mean_y, rcp_std_x, rcp_std_y (B<=1024)
__device__ float g_stats[1024 * 4];

__device__ __forceinline__ float nan0(float v) { return (v != v) ? 0.0f : v; }

// ---------------------------------------------------------------------------
// Kernel A: per-batch nose mean + landmark std (ddof=1) for channels x,y
// ---------------------------------------------------------------------------
__global__ __launch_bounds__(256) void stats_kernel(const float* __restrict__ x) {
    const int b   = blockIdx.x;
    const int tid = threadIdx.x;
    const float* xb = x + (size_t)b * L_FRAMES * NPTS * 3;

    float sx = 0.f, sy = 0.f, qx = 0.f, qy = 0.f, nx = 0.f, ny = 0.f;

    // landmark sums/sumsq over (L, 62)
    const int M = L_FRAMES * NLM;
    for (int i = tid; i < M; i += 256) {
        int l = i / NLM;
        int n = i - l * NLM;
        const float* p = xb + (size_t)l * (NPTS * 3) + c_lm[n] * 3;
        float vx = p[0], vy = p[1];
        vx = (vx != vx) ? 0.0f : vx;
        vy = (vy != vy) ? 0.0f : vy;
        sx += vx; sy += vy;
        qx += vx * vx; qy += vy * vy;
    }

    // nose sums over L (index 17, channels 0,1; NaN -> 0.5)
    for (int l = tid; l < L_FRAMES; l += 256) {
        const float* p = xb + (size_t)l * (NPTS * 3) + 17 * 3;
        float vx = p[0], vy = p[1];
        vx = (vx != vx) ? 0.5f : vx;
        vy = (vy != vy) ? 0.5f : vy;
        nx += vx; ny += vy;
    }

    // block reduction (warp shuffle + shared)
    #pragma unroll
    for (int off = 16; off; off >>= 1) {
        sx += __shfl_down_sync(0xffffffffu, sx, off);
        sy += __shfl_down_sync(0xffffffffu, sy, off);
        qx += __shfl_down_sync(0xffffffffu, qx, off);
        qy += __shfl_down_sync(0xffffffffu, qy, off);
        nx += __shfl_down_sync(0xffffffffu, nx, off);
        ny += __shfl_down_sync(0xffffffffu, ny, off);
    }
    __shared__ float sh[6][8];
    const int wid = tid >> 5, lane = tid & 31;
    if (lane == 0) {
        sh[0][wid] = sx; sh[1][wid] = sy;
        sh[2][wid] = qx; sh[3][wid] = qy;
        sh[4][wid] = nx; sh[5][wid] = ny;
    }
    __syncthreads();
    if (tid == 0) {
        float SX = 0, SY = 0, QX = 0, QY = 0, NX = 0, NY = 0;
        #pragma unroll
        for (int w = 0; w < 8; w++) {
            SX += sh[0][w]; SY += sh[1][w];
            QX += sh[2][w]; QY += sh[3][w];
            NX += sh[4][w]; NY += sh[5][w];
        }
        const float fM = (float)M;
        float varx = (QX - SX * SX / fM) / (fM - 1.0f);
        float vary = (QY - SY * SY / fM) / (fM - 1.0f);
        varx = fmaxf(varx, 0.0f);
        vary = fmaxf(vary, 0.0f);
        g_stats[b * 4 + 0] = NX / (float)L_FRAMES;
        g_stats[b * 4 + 1] = NY / (float)L_FRAMES;
        g_stats[b * 4 + 2] = 1.0f / (sqrtf(varx) + EPS);
        g_stats[b * 4 + 3] = 1.0f / (sqrtf(vary) + EPS);
    }
}

// ---------------------------------------------------------------------------
// Kernel B: main feature computation. One thread per (b, l, n).
// block = (64, 4): threadIdx.x = n (0..61 active), 4 frames per block.
// ---------------------------------------------------------------------------
__global__ __launch_bounds__(256) void main_kernel(const float* __restrict__ x,
                                                   float* __restrict__ out) {
    const int n = threadIdx.x;
    if (n >= NLM) return;
    const int l = blockIdx.x * 4 + threadIdx.y;
    const int b = blockIdx.y;

    const float mx = g_stats[b * 4 + 0];
    const float my = g_stats[b * 4 + 1];
    const float rx = g_stats[b * 4 + 2];
    const float ry = g_stats[b * 4 + 3];

    const float* xb = x + (size_t)b * L_FRAMES * NPTS * 3;
    const int lm = c_lm[n];

    const bool h1 = (l + 1 < L_FRAMES);
    const bool h2 = (l + 2 < L_FRAMES);
    const bool hn = (n + 1 < NLM);

    // normalized xy loader
    auto ld = [&](int ll, int lmi) {
        const float* p = xb + (size_t)ll * (NPTS * 3) + lmi * 3;
        float2 r;
        r.x = (p[0] - mx) * rx;
        r.y = (p[1] - my) * ry;
        return r;
    };

    const float2 xy0 = ld(l, lm);
    float2 xy1 = make_float2(0.f, 0.f), xy2 = make_float2(0.f, 0.f), xyn = make_float2(0.f, 0.f);
    if (h1) xy1 = ld(l + 1, lm);
    if (h2) xy2 = ld(l + 2, lm);
    if (hn) xyn = ld(l, c_lm[n + 1]);

    // dx (padded d)
    float2 d = make_float2(0.f, 0.f);
    if (h1) { d.x = xy1.x - xy0.x; d.y = xy1.y - xy0.y; }
    // dx2
    float2 d2 = make_float2(0.f, 0.f);
    if (h2) { d2.x = xy2.x - xy0.x; d2.y = xy2.y - xy0.y; }
    // relative motion: xy[l+1, n] - xy[l, n+1], padded on last l and last n
    float2 rel = make_float2(0.f, 0.f);
    if (h1 && hn) { rel.x = xy1.x - xyn.x; rel.y = xy1.y - xyn.y; }
    // temporal consistency: cos(d[l], d[l+1]) for l < L-2, else 0
    float tc = 0.f;
    if (h2) {
        const float ax = xy1.x - xy0.x, ay = xy1.y - xy0.y;
        const float bx = xy2.x - xy1.x, by = xy2.y - xy1.y;
        const float na = fmaxf(sqrtf(ax * ax + ay * ay), EPS);
        const float nb = fmaxf(sqrtf(bx * bx + by * by), EPS);
        tc = (ax * bx + ay * by) / (na * nb);
    }
    const float mag = sqrtf(d.x * d.x + d.y * d.y);
    const float dir = atan2f(d.y, d.x);

    float* o = out + ((size_t)b * L_FRAMES + l) * OUTF;

    // nan -> 0 on every output value (identity for this input, matches reference)
    float2 v;
    v.x = nan0(xy0.x); v.y = nan0(xy0.y);
    reinterpret_cast<float2*>(o)[n] = v;                       // [0:124)
    v.x = nan0(d.x);   v.y = nan0(d.y);
    reinterpret_cast<float2*>(o + 124)[n] = v;                 // [124:248)
    v.x = nan0(d2.x);  v.y = nan0(d2.y);
    reinterpret_cast<float2*>(o + 248)[n] = v;                 // [248:372)
    v.x = nan0(rel.x); v.y = nan0(rel.y);
    reinterpret_cast<float2*>(o + 372)[n] = v;                 // [372:496)
    const float tcz = nan0(tc);
    v.x = tcz; v.y = tcz;
    reinterpret_cast<float2*>(o + 496)[n] = v;                 // [496:620)
    o[620 + n] = nan0(mag);                                    // [620:682)
    o[682 + n] = nan0(dir);                                    // [682:744)
}

// ---------------------------------------------------------------------------
extern "C" void kernel_launch(void* const* d_in, const int* in_sizes, int n_in,
                              void* d_out, int out_size) {
    const float* x = (const float*)d_in[0];
    float* out = (float*)d_out;

    const int B = in_sizes[0] / (L_FRAMES * NPTS * 3);

    stats_kernel<<<B, 256>>>(x);

    dim3 blk(64, 4);
    dim3 grd(L_FRAMES / 4, B);
    main_kernel<<<grd, blk>>>(x, out);
}

// round 2
// speedup vs baseline: 1.0869x; 1.0869x over previous
#include <cuda_runtime.h>
#include <math.h>

#define EPS 1e-8f
#define L_FRAMES 384
#define NPTS 543
#define NLM 62
#define OUTF 744      // 5*124 + 2*62
#define ROWF (NPTS*3) // 1629
#define FPB 8         // frames per block in main kernel
#define SF (FPB + 2)  // staged frames
#define NSEG 8        // stats partial segments per batch
#define FSEG (L_FRAMES / NSEG) // 48

__constant__ int c_lm[NLM] = {
    33,133,362,263,61,291,199,419,17,84,17,314,405,320,307,375,321,308,324,318,
    501,502,503,504,505,506,507,508,509,510,511,512,513,514,515,516,517,518,519,520,521,
    522,523,524,525,526,527,528,529,530,531,532,533,534,535,536,537,538,539,540,541,542
};

// per-batch stats: mean_x, mean_y, rcp_std_x, rcp_std_y
__device__ float g_stats[1024 * 4];
// partial sums: [b][seg][6] = sx, sy, qx, qy, nose_x, nose_y
__device__ float g_part[1024 * NSEG * 6];

__device__ __forceinline__ float nan0(float v) { return (v != v) ? 0.0f : v; }

// ---------------------------------------------------------------------------
// Kernel A1: partial sums over a 48-frame segment of one batch.
// grid = (B, NSEG), block = 256. Deterministic (block-local reduction only).
// ---------------------------------------------------------------------------
__global__ __launch_bounds__(256) void stats_partial_kernel(const float* __restrict__ x) {
    const int b   = blockIdx.x;
    const int seg = blockIdx.y;
    const int tid = threadIdx.x;
    const float* xb = x + (size_t)b * L_FRAMES * ROWF;
    const int l0 = seg * FSEG;

    float sx = 0.f, sy = 0.f, qx = 0.f, qy = 0.f, nx = 0.f, ny = 0.f;

    const int M = FSEG * NLM; // 2976
    for (int i = tid; i < M; i += 256) {
        const int l = l0 + i / NLM;
        const int n = i - (i / NLM) * NLM;
        const float* p = xb + (size_t)l * ROWF + c_lm[n] * 3;
        float vx = __ldg(p), vy = __ldg(p + 1);
        vx = (vx != vx) ? 0.0f : vx;
        vy = (vy != vy) ? 0.0f : vy;
        sx += vx; sy += vy;
        qx = fmaf(vx, vx, qx); qy = fmaf(vy, vy, qy);
    }

    if (tid < FSEG) {
        const float* p = xb + (size_t)(l0 + tid) * ROWF + 17 * 3;
        float vx = __ldg(p), vy = __ldg(p + 1);
        vx = (vx != vx) ? 0.5f : vx;
        vy = (vy != vy) ? 0.5f : vy;
        nx = vx; ny = vy;
    }

    #pragma unroll
    for (int off = 16; off; off >>= 1) {
        sx += __shfl_down_sync(0xffffffffu, sx, off);
        sy += __shfl_down_sync(0xffffffffu, sy, off);
        qx += __shfl_down_sync(0xffffffffu, qx, off);
        qy += __shfl_down_sync(0xffffffffu, qy, off);
        nx += __shfl_down_sync(0xffffffffu, nx, off);
        ny += __shfl_down_sync(0xffffffffu, ny, off);
    }
    __shared__ float sh[6][8];
    const int wid = tid >> 5, lane = tid & 31;
    if (lane == 0) {
        sh[0][wid] = sx; sh[1][wid] = sy;
        sh[2][wid] = qx; sh[3][wid] = qy;
        sh[4][wid] = nx; sh[5][wid] = ny;
    }
    __syncthreads();
    if (tid < 6) {
        float v = 0.f;
        #pragma unroll
        for (int w = 0; w < 8; w++) v += sh[tid][w];
        g_part[((size_t)b * NSEG + seg) * 6 + tid] = v;
    }
}

// ---------------------------------------------------------------------------
// Kernel A2: finalize per-batch stats (one thread per batch).
// ---------------------------------------------------------------------------
__global__ void stats_finalize_kernel(int B) {
    const int b = blockIdx.x * blockDim.x + threadIdx.x;
    if (b >= B) return;
    float S[6] = {0.f, 0.f, 0.f, 0.f, 0.f, 0.f};
    #pragma unroll
    for (int s = 0; s < NSEG; s++) {
        #pragma unroll
        for (int j = 0; j < 6; j++) S[j] += g_part[((size_t)b * NSEG + s) * 6 + j];
    }
    const float fM = (float)(L_FRAMES * NLM);
    float varx = (S[2] - S[0] * S[0] / fM) / (fM - 1.0f);
    float vary = (S[3] - S[1] * S[1] / fM) / (fM - 1.0f);
    varx = fmaxf(varx, 0.0f);
    vary = fmaxf(vary, 0.0f);
    g_stats[b * 4 + 0] = S[4] / (float)L_FRAMES;
    g_stats[b * 4 + 1] = S[5] / (float)L_FRAMES;
    g_stats[b * 4 + 2] = 1.0f / (sqrtf(varx) + EPS);
    g_stats[b * 4 + 3] = 1.0f / (sqrtf(vary) + EPS);
}

// ---------------------------------------------------------------------------
// Kernel B: main feature computation.
// block = (64, 4) = 256 threads, each block covers FPB=8 frames of one batch
// (each thread computes 2 frames). Input points staged+normalized in SMEM,
// each point loaded exactly once per block.
// ---------------------------------------------------------------------------
__global__ __launch_bounds__(256) void main_kernel(const float* __restrict__ x,
                                                   float* __restrict__ out) {
    const int b = blockIdx.y;
    const int l_base = blockIdx.x * FPB;
    const int tid = threadIdx.y * 64 + threadIdx.x;

    const float mx = g_stats[b * 4 + 0];
    const float my = g_stats[b * 4 + 1];
    const float rx = g_stats[b * 4 + 2];
    const float ry = g_stats[b * 4 + 3];

    const float* xb = x + (size_t)b * L_FRAMES * ROWF;

    __shared__ float2 s[SF][NLM];

    // cooperative staging: SF*62 = 620 points, 256 threads, ~3 iterations
    for (int i = tid; i < SF * NLM; i += 256) {
        const int f = i / NLM;
        const int n = i - f * NLM;
        const int fr = min(l_base + f, L_FRAMES - 1);
        const float* p = xb + (size_t)fr * ROWF + c_lm[n] * 3;
        s[f][n] = make_float2((__ldg(p) - mx) * rx, (__ldg(p + 1) - my) * ry);
    }
    __syncthreads();

    const int n = threadIdx.x;
    if (n >= NLM) return;
    const int np = (n + 1 < NLM) ? (n + 1) : n; // safe smem read; gated by hn
    const bool hn = (n + 1 < NLM);

    #pragma unroll
    for (int k = 0; k < 2; k++) {
        const int ly = threadIdx.y + k * 4;
        const int l = l_base + ly;

        const bool h1 = (l + 1 < L_FRAMES);
        const bool h2 = (l + 2 < L_FRAMES);

        const float2 xy0 = s[ly][n];
        const float2 xy1 = s[ly + 1][n];
        const float2 xy2 = s[ly + 2][n];
        const float2 xyn = s[ly][np];

        float2 d = make_float2(0.f, 0.f);
        if (h1) { d.x = xy1.x - xy0.x; d.y = xy1.y - xy0.y; }
        float2 d2 = make_float2(0.f, 0.f);
        if (h2) { d2.x = xy2.x - xy0.x; d2.y = xy2.y - xy0.y; }
        float2 rel = make_float2(0.f, 0.f);
        if (h1 && hn) { rel.x = xy1.x - xyn.x; rel.y = xy1.y - xyn.y; }
        float tc = 0.f;
        if (h2) {
            const float ax = xy1.x - xy0.x, ay = xy1.y - xy0.y;
            const float bx = xy2.x - xy1.x, by = xy2.y - xy1.y;
            const float na = fmaxf(sqrtf(ax * ax + ay * ay), EPS);
            const float nb = fmaxf(sqrtf(bx * bx + by * by), EPS);
            tc = (ax * bx + ay * by) / (na * nb);
        }
        const float mag = sqrtf(d.x * d.x + d.y * d.y);
        const float dir = atan2f(d.y, d.x);

        float* o = out + ((size_t)b * L_FRAMES + l) * OUTF;

        float2 v;
        v.x = nan0(xy0.x); v.y = nan0(xy0.y);
        reinterpret_cast<float2*>(o)[n] = v;                   // [0:124)
        v.x = nan0(d.x);   v.y = nan0(d.y);
        reinterpret_cast<float2*>(o + 124)[n] = v;             // [124:248)
        v.x = nan0(d2.x);  v.y = nan0(d2.y);
        reinterpret_cast<float2*>(o + 248)[n] = v;             // [248:372)
        v.x = nan0(rel.x); v.y = nan0(rel.y);
        reinterpret_cast<float2*>(o + 372)[n] = v;             // [372:496)
        const float tcz = nan0(tc);
        v.x = tcz; v.y = tcz;
        reinterpret_cast<float2*>(o + 496)[n] = v;             // [496:620)
        o[620 + n] = nan0(mag);                                // [620:682)
        o[682 + n] = nan0(dir);                                // [682:744)
    }
}

// ---------------------------------------------------------------------------
extern "C" void kernel_launch(void* const* d_in, const int* in_sizes, int n_in,
                              void* d_out, int out_size) {
    const float* x = (const float*)d_in[0];
    float* out = (float*)d_out;

    const int B = in_sizes[0] / (L_FRAMES * ROWF);

    dim3 sgrid(B, NSEG);
    stats_partial_kernel<<<sgrid, 256>>>(x);
    stats_finalize_kernel<<<(B + 255) / 256, 256>>>(B);

    dim3 blk(64, 4);
    dim3 grd(L_FRAMES / FPB, B);
    main_kernel<<<grd, blk>>>(x, out);
}

// round 3
// speedup vs baseline: 1.2952x; 1.1916x over previous
#include <cuda_runtime.h>
#include <math.h>

#define EPS 1e-8f
#define L_FRAMES 384
#define NPTS 543
#define NLM 62
#define OUTF 744      // 5*124 + 2*62
#define ROWF (NPTS*3) // 1629
#define FPB 16        // frames per block in pass-2 kernel
#define SF (FPB + 2)  // staged frames (halo of 2)
#define NSEG 8        // stats partial segments per batch
#define FSEG (L_FRAMES / NSEG) // 48
#define MAXB 256

__constant__ int c_lm[NLM] = {
    33,133,362,263,61,291,199,419,17,84,17,314,405,320,307,375,321,308,324,318,
    501,502,503,504,505,506,507,508,509,510,511,512,513,514,515,516,517,518,519,520,521,
    522,523,524,525,526,527,528,529,530,531,532,533,534,535,536,537,538,539,540,541,542
};

// per-batch stats: mean_x, mean_y, rcp_std_x, rcp_std_y
__device__ float g_stats[1024 * 4];
// partial sums: [b][seg][6] = sx, sy, qx, qy, nose_x, nose_y
__device__ float g_part[1024 * NSEG * 6];
// compact gathered landmarks (raw, NaN preserved): [b][l][n][2]
__device__ float2 g_comp[MAXB * L_FRAMES * NLM];

__device__ __forceinline__ float nan0(float v) { return (v != v) ? 0.0f : v; }

// ---------------------------------------------------------------------------
// Pass 1: gather landmarks into compact buffer + partial sums.
// grid = (B, NSEG), block = (64, 4). Each block: 48 frames of one batch.
// ---------------------------------------------------------------------------
__global__ __launch_bounds__(256) void gather_stats_kernel(const float* __restrict__ x) {
    const int b   = blockIdx.x;
    const int seg = blockIdx.y;
    const int n   = threadIdx.x;
    const int fy  = threadIdx.y;
    const int tid = fy * 64 + n;
    const float* xb = x + (size_t)b * L_FRAMES * ROWF;
    const int l0 = seg * FSEG;

    float sx = 0.f, sy = 0.f, qx = 0.f, qy = 0.f, nx = 0.f, ny = 0.f;

    if (n < NLM) {
        const int lm3 = c_lm[n] * 3;
        const bool is_nose = (n == 8);   // c_lm[8] == 17 (nose)
        #pragma unroll 4
        for (int f = fy; f < FSEG; f += 4) {
            const int l = l0 + f;
            const float* p = xb + (size_t)l * ROWF + lm3;
            const float vx = __ldg(p);
            const float vy = __ldg(p + 1);
            // compact raw (NaN preserved)
            g_comp[((size_t)b * L_FRAMES + l) * NLM + n] = make_float2(vx, vy);
            // cleaned for std sums
            const float cx = (vx != vx) ? 0.0f : vx;
            const float cy = (vy != vy) ? 0.0f : vy;
            sx += cx; sy += cy;
            qx = fmaf(cx, cx, qx); qy = fmaf(cy, cy, qy);
            if (is_nose) {
                nx += (vx != vx) ? 0.5f : vx;
                ny += (vy != vy) ? 0.5f : vy;
            }
        }
    }

    // block reduction
    #pragma unroll
    for (int off = 16; off; off >>= 1) {
        sx += __shfl_down_sync(0xffffffffu, sx, off);
        sy += __shfl_down_sync(0xffffffffu, sy, off);
        qx += __shfl_down_sync(0xffffffffu, qx, off);
        qy += __shfl_down_sync(0xffffffffu, qy, off);
        nx += __shfl_down_sync(0xffffffffu, nx, off);
        ny += __shfl_down_sync(0xffffffffu, ny, off);
    }
    __shared__ float sh[6][8];
    const int wid = tid >> 5, lane = tid & 31;
    if (lane == 0) {
        sh[0][wid] = sx; sh[1][wid] = sy;
        sh[2][wid] = qx; sh[3][wid] = qy;
        sh[4][wid] = nx; sh[5][wid] = ny;
    }
    __syncthreads();
    if (tid < 6) {
        float v = 0.f;
        #pragma unroll
        for (int w = 0; w < 8; w++) v += sh[tid][w];
        g_part[((size_t)b * NSEG + seg) * 6 + tid] = v;
    }
}

// ---------------------------------------------------------------------------
// Finalize per-batch stats (one thread per batch).
// ---------------------------------------------------------------------------
__global__ void stats_finalize_kernel(int B) {
    const int b = blockIdx.x * blockDim.x + threadIdx.x;
    if (b >= B) return;
    float S[6] = {0.f, 0.f, 0.f, 0.f, 0.f, 0.f};
    #pragma unroll
    for (int s = 0; s < NSEG; s++) {
        #pragma unroll
        for (int j = 0; j < 6; j++) S[j] += g_part[((size_t)b * NSEG + s) * 6 + j];
    }
    const float fM = (float)(L_FRAMES * NLM);
    float varx = (S[2] - S[0] * S[0] / fM) / (fM - 1.0f);
    float vary = (S[3] - S[1] * S[1] / fM) / (fM - 1.0f);
    varx = fmaxf(varx, 0.0f);
    vary = fmaxf(vary, 0.0f);
    g_stats[b * 4 + 0] = S[4] / (float)L_FRAMES;
    g_stats[b * 4 + 1] = S[5] / (float)L_FRAMES;
    g_stats[b * 4 + 2] = 1.0f / (sqrtf(varx) + EPS);
    g_stats[b * 4 + 3] = 1.0f / (sqrtf(vary) + EPS);
}

// ---------------------------------------------------------------------------
// Pass 2: features from the compact buffer (no access to x).
// block = (64, 4) = 256 threads, FPB=16 frames per block, 4 frames/thread.
// ---------------------------------------------------------------------------
__global__ __launch_bounds__(256) void main_kernel(float* __restrict__ out) {
    const int b = blockIdx.y;
    const int l_base = blockIdx.x * FPB;
    const int tid = threadIdx.y * 64 + threadIdx.x;

    const float mx = g_stats[b * 4 + 0];
    const float my = g_stats[b * 4 + 1];
    const float rx = g_stats[b * 4 + 2];
    const float ry = g_stats[b * 4 + 3];

    __shared__ float2 s[SF][NLM];

    // stage SF*62 = 1116 normalized points; compact reads are coalesced
    const float2* cb = g_comp + (size_t)b * L_FRAMES * NLM;
    for (int i = tid; i < SF * NLM; i += 256) {
        const int f = i / NLM;
        const int n = i - f * NLM;
        const int fr = min(l_base + f, L_FRAMES - 1);
        const float2 r = cb[(size_t)fr * NLM + n];
        s[f][n] = make_float2((r.x - mx) * rx, (r.y - my) * ry);
    }
    __syncthreads();

    const int n = threadIdx.x;
    if (n >= NLM) return;
    const int np = (n + 1 < NLM) ? (n + 1) : n;
    const bool hn = (n + 1 < NLM);

    #pragma unroll
    for (int k = 0; k < FPB / 4; k++) {
        const int ly = threadIdx.y + k * 4;
        const int l = l_base + ly;

        const bool h1 = (l + 1 < L_FRAMES);
        const bool h2 = (l + 2 < L_FRAMES);

        const float2 xy0 = s[ly][n];
        const float2 xy1 = s[ly + 1][n];
        const float2 xy2 = s[ly + 2][n];
        const float2 xyn = s[ly][np];

        float2 d = make_float2(0.f, 0.f);
        if (h1) { d.x = xy1.x - xy0.x; d.y = xy1.y - xy0.y; }
        float2 d2 = make_float2(0.f, 0.f);
        if (h2) { d2.x = xy2.x - xy0.x; d2.y = xy2.y - xy0.y; }
        float2 rel = make_float2(0.f, 0.f);
        if (h1 && hn) { rel.x = xy1.x - xyn.x; rel.y = xy1.y - xyn.y; }
        float tc = 0.f;
        if (h2) {
            const float ax = xy1.x - xy0.x, ay = xy1.y - xy0.y;
            const float bx = xy2.x - xy1.x, by = xy2.y - xy1.y;
            const float na = fmaxf(sqrtf(ax * ax + ay * ay), EPS);
            const float nb = fmaxf(sqrtf(bx * bx + by * by), EPS);
            tc = (ax * bx + ay * by) / (na * nb);
        }
        const float mag = sqrtf(d.x * d.x + d.y * d.y);
        const float dir = atan2f(d.y, d.x);

        float* o = out + ((size_t)b * L_FRAMES + l) * OUTF;

        float2 v;
        v.x = nan0(xy0.x); v.y = nan0(xy0.y);
        reinterpret_cast<float2*>(o)[n] = v;                   // [0:124)
        v.x = nan0(d.x);   v.y = nan0(d.y);
        reinterpret_cast<float2*>(o + 124)[n] = v;             // [124:248)
        v.x = nan0(d2.x);  v.y = nan0(d2.y);
        reinterpret_cast<float2*>(o + 248)[n] = v;             // [248:372)
        v.x = nan0(rel.x); v.y = nan0(rel.y);
        reinterpret_cast<float2*>(o + 372)[n] = v;             // [372:496)
        const float tcz = nan0(tc);
        v.x = tcz; v.y = tcz;
        reinterpret_cast<float2*>(o + 496)[n] = v;             // [496:620)
        o[620 + n] = nan0(mag);                                // [620:682)
        o[682 + n] = nan0(dir);                                // [682:744)
    }
}

// ---------------------------------------------------------------------------
extern "C" void kernel_launch(void* const* d_in, const int* in_sizes, int n_in,
                              void* d_out, int out_size) {
    const float* x = (const float*)d_in[0];
    float* out = (float*)d_out;

    const int B = in_sizes[0] / (L_FRAMES * ROWF);

    dim3 sgrid(B, NSEG);
    dim3 sblk(64, 4);
    gather_stats_kernel<<<sgrid, sblk>>>(x);
    stats_finalize_kernel<<<(B + 255) / 256, 256>>>(B);

    dim3 blk(64, 4);
    dim3 grd(L_FRAMES / FPB, B);
    main_kernel<<<grd, blk>>>(out);
}